// round 1
// baseline (speedup 1.0000x reference)
#include <cuda_runtime.h>
#include <cuda_bf16.h>
#include <math.h>

// Problem constants
#define V_  30000
#define E_  256
#define H_  512
#define B_  64
#define S_  64

// ---------------- device scratch (static, allocation-free) ----------------
__device__ float g_GI[(size_t)S_ * B_ * (3 * H_)];       // encoder input gates [t][b][3H]  (~25 MB)
__device__ float g_enc_outs[(size_t)B_ * S_ * H_];       // [b][t][H]  (8 MB)
__device__ float g_temp[(size_t)B_ * S_ * H_];           // [b][s][H]  (8 MB)
__device__ float g_xc[(size_t)B_ * (2 * H_)];            // [b][ h(512) | context(512) ]
__device__ float g_hprev[(size_t)B_ * H_];               // decoder h_{t-1}
__device__ float g_demb[(size_t)B_ * E_];                // decoder input embedding

__device__ __forceinline__ float sigmoidf_(float x) {
    return 1.0f / (1.0f + expf(-x));
}

// ---------------- generic tiled SGEMM:  C[m][n] = sum_k A[m][k]*B[n][k] + bias[n] ----
// BM=BN=64, KC=32, 256 threads, 4x4 register tile. K%32==0, M%64==0 required.
// If gather != null, row m of A is  A + gather[(m%64)*64 + (m/64)] * K   (embedding gather).
#define BM 64
#define BN 64
#define KC 32

__global__ void __launch_bounds__(256) gemm_nt_kernel(
    const float* __restrict__ A, const float* __restrict__ B,
    const float* __restrict__ bias, float* __restrict__ C,
    int M, int N, int K, int ldc, const int* __restrict__ gather)
{
    __shared__ float As[KC][BM];
    __shared__ float Bs[KC][BN];

    const int bn = blockIdx.x * BN;
    const int bm = blockIdx.y * BM;
    const int tid = threadIdx.x;
    const int tn = tid & 15;        // 0..15  (n direction)
    const int tm = tid >> 4;        // 0..15  (m direction)

    float acc[4][4];
#pragma unroll
    for (int i = 0; i < 4; i++)
#pragma unroll
        for (int j = 0; j < 4; j++) acc[i][j] = 0.f;

    for (int k0 = 0; k0 < K; k0 += KC) {
        // ---- stage A tile (64 rows x 32 k) and B tile ----
#pragma unroll
        for (int u = 0; u < 2; u++) {
            int f   = tid + u * 256;       // 0..511 : 64 rows * 8 float4
            int row = f >> 3;
            int kq  = f & 7;

            // A
            const float* ap;
            int m = bm + row;
            if (gather) {
                int bb = m & 63, tt = m >> 6;
                ap = A + (size_t)gather[bb * 64 + tt] * K;
            } else {
                ap = A + (size_t)m * K;
            }
            float4 va = *(const float4*)(ap + k0 + kq * 4);
            As[kq * 4 + 0][row] = va.x;
            As[kq * 4 + 1][row] = va.y;
            As[kq * 4 + 2][row] = va.z;
            As[kq * 4 + 3][row] = va.w;

            // B (guard n)
            int n = bn + row;
            float4 vb;
            if (n < N) vb = *(const float4*)(B + (size_t)n * K + k0 + kq * 4);
            else       vb = make_float4(0.f, 0.f, 0.f, 0.f);
            Bs[kq * 4 + 0][row] = vb.x;
            Bs[kq * 4 + 1][row] = vb.y;
            Bs[kq * 4 + 2][row] = vb.z;
            Bs[kq * 4 + 3][row] = vb.w;
        }
        __syncthreads();

#pragma unroll
        for (int kk = 0; kk < KC; kk++) {
            float4 a4 = *(const float4*)&As[kk][tm * 4];
            float4 b4 = *(const float4*)&Bs[kk][tn * 4];
            float av[4] = {a4.x, a4.y, a4.z, a4.w};
            float bv[4] = {b4.x, b4.y, b4.z, b4.w};
#pragma unroll
            for (int i = 0; i < 4; i++)
#pragma unroll
                for (int j = 0; j < 4; j++)
                    acc[i][j] += av[i] * bv[j];
        }
        __syncthreads();
    }

    // ---- epilogue: + bias, store ----
#pragma unroll
    for (int i = 0; i < 4; i++) {
        int m = bm + tm * 4 + i;
        int n = bn + tn * 4;
        if (n + 3 < N) {
            float4 o;
            o.x = acc[i][0] + bias[n + 0];
            o.y = acc[i][1] + bias[n + 1];
            o.z = acc[i][2] + bias[n + 2];
            o.w = acc[i][3] + bias[n + 3];
            *(float4*)(C + (size_t)m * ldc + n) = o;
        } else {
#pragma unroll
            for (int j = 0; j < 4; j++)
                if (n + j < N) C[(size_t)m * ldc + n + j] = acc[i][j] + bias[n + j];
        }
    }
}

// ---------------- encoder GRU step (fused gh-dots + gate) --------------------
// grid: (H/64=8, B=64), 256 threads. Each block: b, i in [i0,i0+64).
// Computes gh for rows {i, H+i, 2H+i}, combines with precomputed GI, gates, writes enc_outs[b][t].
__global__ void __launch_bounds__(256) enc_step_kernel(
    int t, const float* __restrict__ Whh, const float* __restrict__ bhh)
{
    const int b = blockIdx.y;
    const int i0 = blockIdx.x * 64;
    const int tid = threadIdx.x;

    __shared__ float sh_h[H_];
    __shared__ float sh_g[192];

    for (int i = tid; i < H_; i += 256)
        sh_h[i] = (t == 0) ? 0.f : g_enc_outs[((size_t)b * S_ + (t - 1)) * H_ + i];
    __syncthreads();

    const int w = tid >> 5, lane = tid & 31;
#pragma unroll 1
    for (int q = 0; q < 24; q++) {
        int d = w * 24 + q;              // 0..191
        int g = d >> 6, ii = d & 63;
        int row = g * H_ + i0 + ii;
        const float* wr = Whh + (size_t)row * H_;
        float s = 0.f;
#pragma unroll
        for (int it = 0; it < 4; it++) {
            int k = lane * 4 + it * 128;
            float4 wv = *(const float4*)(wr + k);
            float4 hv = *(const float4*)(sh_h + k);
            s += wv.x * hv.x + wv.y * hv.y + wv.z * hv.z + wv.w * hv.w;
        }
#pragma unroll
        for (int o = 16; o > 0; o >>= 1) s += __shfl_down_sync(0xffffffffu, s, o);
        if (lane == 0) sh_g[d] = s + bhh[row];
    }
    __syncthreads();

    if (tid < 64) {
        int i = i0 + tid;
        const float* gi = g_GI + ((size_t)t * B_ + b) * (3 * H_);
        float r = sigmoidf_(gi[i]            + sh_g[tid]);
        float z = sigmoidf_(gi[H_ + i]       + sh_g[64 + tid]);
        float n = tanhf   (gi[2 * H_ + i] + r * sh_g[128 + tid]);
        g_enc_outs[((size_t)b * S_ + t) * H_ + i] = (1.f - z) * n + z * sh_h[i];
    }
}

// ---------------- decoder GRU step (gi + gh dots + gate, fused) --------------
// grid (8, 64), 256 threads. Reads g_demb, g_xc[b][512:](old context), g_hprev.
// Writes new h into g_xc[b][0:512].
__global__ void __launch_bounds__(256) dec_gru_kernel(
    const float* __restrict__ Wih, const float* __restrict__ Whh,
    const float* __restrict__ bih, const float* __restrict__ bhh)
{
    const int b = blockIdx.y;
    const int i0 = blockIdx.x * 64;
    const int tid = threadIdx.x;

    __shared__ float sh_in[E_ + H_];   // 768 : [dec_emb | context]
    __shared__ float sh_h[H_];
    __shared__ float sh_gi[192];
    __shared__ float sh_gh[192];

    for (int i = tid; i < E_; i += 256)  sh_in[i]       = g_demb[(size_t)b * E_ + i];
    for (int i = tid; i < H_; i += 256)  sh_in[E_ + i]  = g_xc[(size_t)b * (2 * H_) + H_ + i];
    for (int i = tid; i < H_; i += 256)  sh_h[i]        = g_hprev[(size_t)b * H_ + i];
    __syncthreads();

    const int w = tid >> 5, lane = tid & 31;
#pragma unroll 1
    for (int q = 0; q < 48; q++) {
        int d = w * 48 + q;              // 0..383
        float s = 0.f;
        if (d < 192) {                   // gi: K = 768
            int g = d >> 6, ii = d & 63;
            int row = g * H_ + i0 + ii;
            const float* wr = Wih + (size_t)row * (E_ + H_);
#pragma unroll
            for (int it = 0; it < 6; it++) {
                int k = lane * 4 + it * 128;
                float4 wv = *(const float4*)(wr + k);
                float4 xv = *(const float4*)(sh_in + k);
                s += wv.x * xv.x + wv.y * xv.y + wv.z * xv.z + wv.w * xv.w;
            }
#pragma unroll
            for (int o = 16; o > 0; o >>= 1) s += __shfl_down_sync(0xffffffffu, s, o);
            if (lane == 0) sh_gi[d] = s + bih[row];
        } else {                         // gh: K = 512
            int d2 = d - 192;
            int g = d2 >> 6, ii = d2 & 63;
            int row = g * H_ + i0 + ii;
            const float* wr = Whh + (size_t)row * H_;
#pragma unroll
            for (int it = 0; it < 4; it++) {
                int k = lane * 4 + it * 128;
                float4 wv = *(const float4*)(wr + k);
                float4 hv = *(const float4*)(sh_h + k);
                s += wv.x * hv.x + wv.y * hv.y + wv.z * hv.z + wv.w * hv.w;
            }
#pragma unroll
            for (int o = 16; o > 0; o >>= 1) s += __shfl_down_sync(0xffffffffu, s, o);
            if (lane == 0) sh_gh[d2] = s + bhh[row];
        }
    }
    __syncthreads();

    if (tid < 64) {
        int i = i0 + tid;
        float r = sigmoidf_(sh_gi[tid]       + sh_gh[tid]);
        float z = sigmoidf_(sh_gi[64 + tid]  + sh_gh[64 + tid]);
        float n = tanhf   (sh_gi[128 + tid] + r * sh_gh[128 + tid]);
        g_xc[(size_t)b * (2 * H_) + i] = (1.f - z) * n + z * sh_h[i];
    }
}

// ---------------- argmax + embedding feedback + attention --------------------
// grid 64 (block per batch), 256 threads.
__global__ void __launch_bounds__(256) attn_argmax_kernel(
    int t, int ML, const float* __restrict__ scores_base,
    const float* __restrict__ emb)
{
    const int b = blockIdx.x;
    const int tid = threadIdx.x;

    __shared__ float s_v[256];
    __shared__ int   s_i[256];
    __shared__ float sh_h[H_];
    __shared__ float sh_e[S_];
    __shared__ float sh_a[S_];

    // ---- argmax over V (first-occurrence tie-break, matching jnp.argmax) ----
    const float* row = scores_base + ((size_t)b * ML + t) * V_;
    float bv = -3.4e38f;
    int bi = 0;
    for (int v = tid; v < V_; v += 256) {
        float sv = row[v];
        if (sv > bv) { bv = sv; bi = v; }
    }
    s_v[tid] = bv; s_i[tid] = bi;
    __syncthreads();
#pragma unroll
    for (int o = 128; o > 0; o >>= 1) {
        if (tid < o) {
            if (s_v[tid + o] > s_v[tid] ||
                (s_v[tid + o] == s_v[tid] && s_i[tid + o] < s_i[tid])) {
                s_v[tid] = s_v[tid + o];
                s_i[tid] = s_i[tid + o];
            }
        }
        __syncthreads();
    }
    const int idx = s_i[0];

    // dec_emb = emb[idx]
    if (tid < E_) g_demb[(size_t)b * E_ + tid] = emb[(size_t)idx * E_ + tid];

    // ---- attention: alpha = softmax(temp[b] . h), context = alpha . enc_outs[b] ----
    for (int i = tid; i < H_; i += 256) sh_h[i] = g_xc[(size_t)b * (2 * H_) + i];
    __syncthreads();

    const int w = tid >> 5, lane = tid & 31;
#pragma unroll 1
    for (int q = 0; q < 8; q++) {
        int s = w * 8 + q;               // 0..63
        const float* tr = g_temp + ((size_t)b * S_ + s) * H_;
        float e = 0.f;
#pragma unroll
        for (int it = 0; it < 4; it++) {
            int k = lane * 4 + it * 128;
            float4 tv = *(const float4*)(tr + k);
            float4 hv = *(const float4*)(sh_h + k);
            e += tv.x * hv.x + tv.y * hv.y + tv.z * hv.z + tv.w * hv.w;
        }
#pragma unroll
        for (int o = 16; o > 0; o >>= 1) e += __shfl_down_sync(0xffffffffu, e, o);
        if (lane == 0) sh_e[s] = e;
    }
    __syncthreads();

    if (tid == 0) {
        float m = sh_e[0];
        for (int s = 1; s < S_; s++) m = fmaxf(m, sh_e[s]);
        float sum = 0.f;
        for (int s = 0; s < S_; s++) { float ex = expf(sh_e[s] - m); sh_a[s] = ex; sum += ex; }
        float inv = 1.f / sum;
        for (int s = 0; s < S_; s++) sh_a[s] *= inv;
    }
    __syncthreads();

    // context + carry h -> h_prev
    for (int i = tid; i < H_; i += 256) {
        float c = 0.f;
        const float* eo = g_enc_outs + (size_t)b * S_ * H_ + i;
#pragma unroll 4
        for (int s = 0; s < S_; s++) c += sh_a[s] * eo[(size_t)s * H_];
        g_xc[(size_t)b * (2 * H_) + H_ + i] = c;
        g_hprev[(size_t)b * H_ + i] = sh_h[i];
    }
}

// ---------------- decoder init --------------------------------------------
__global__ void __launch_bounds__(256) init_kernel(
    const int* __restrict__ start_decode, const float* __restrict__ emb)
{
    const int b = blockIdx.x;
    const int tid = threadIdx.x;
    for (int i = tid; i < H_; i += 256) {
        float v = g_enc_outs[((size_t)b * S_ + (S_ - 1)) * H_ + i];  // h_enc
        g_hprev[(size_t)b * H_ + i] = v;
        g_xc[(size_t)b * (2 * H_) + H_ + i] = v;                    // context0
    }
    if (tid < E_) {
        int idx = start_decode[b];
        g_demb[(size_t)b * E_ + tid] = emb[(size_t)idx * E_ + tid];
    }
}

// ---------------- launch ---------------------------------------------------
extern "C" void kernel_launch(void* const* d_in, const int* in_sizes, int n_in,
                              void* d_out, int out_size)
{
    const int*   x    = (const int*)  d_in[0];
    const int*   sd   = (const int*)  d_in[1];
    // d_in[2] = max_len scalar (value known from out_size)
    const float* emb  = (const float*)d_in[3];
    const float* eWih = (const float*)d_in[4];
    const float* eWhh = (const float*)d_in[5];
    const float* ebih = (const float*)d_in[6];
    const float* ebhh = (const float*)d_in[7];
    const float* dWih = (const float*)d_in[8];
    const float* dWhh = (const float*)d_in[9];
    const float* dbih = (const float*)d_in[10];
    const float* dbhh = (const float*)d_in[11];
    const float* fcW  = (const float*)d_in[12];
    const float* fcb  = (const float*)d_in[13];
    const float* aW   = (const float*)d_in[14];
    const float* ab   = (const float*)d_in[15];
    float* out = (float*)d_out;

    const int ML = out_size / (B_ * V_);   // = 32

    float *pGI = nullptr, *pEnc = nullptr, *pTemp = nullptr, *pXc = nullptr;
    cudaGetSymbolAddress((void**)&pGI,   g_GI);
    cudaGetSymbolAddress((void**)&pEnc,  g_enc_outs);
    cudaGetSymbolAddress((void**)&pTemp, g_temp);
    cudaGetSymbolAddress((void**)&pXc,   g_xc);

    // 1) Encoder input gates for all timesteps: GI[t*B+b][j] = emb[x[b][t]] . eWih[j] + ebih[j]
    {
        dim3 grid((3 * H_) / BN, (S_ * B_) / BM);
        gemm_nt_kernel<<<grid, 256>>>(emb, eWih, ebih, pGI,
                                      S_ * B_, 3 * H_, E_, 3 * H_, x);
    }

    // 2) Encoder recurrence
    for (int t = 0; t < S_; t++)
        enc_step_kernel<<<dim3(H_ / 64, B_), 256>>>(t, eWhh, ebhh);

    // 3) temp = enc_outs @ attn_W^T + attn_b
    {
        dim3 grid(H_ / BN, (B_ * S_) / BM);
        gemm_nt_kernel<<<grid, 256>>>(pEnc, aW, ab, pTemp,
                                      B_ * S_, H_, H_, H_, nullptr);
    }

    // 4) decoder init
    init_kernel<<<B_, 256>>>(sd, emb);

    // 5) decoder loop
    for (int t = 0; t < ML; t++) {
        dec_gru_kernel<<<dim3(H_ / 64, B_), 256>>>(dWih, dWhh, dbih, dbhh);

        // scores -> d_out rows (b*ML + t)
        dim3 grid((V_ + BN - 1) / BN, 1);
        gemm_nt_kernel<<<grid, 256>>>(pXc, fcW, fcb, out + (size_t)t * V_,
                                      B_, V_, 2 * H_, ML * V_, nullptr);

        attn_argmax_kernel<<<B_, 256>>>(t, ML, out, emb);
    }
}